// round 5
// baseline (speedup 1.0000x reference)
#include <cuda_runtime.h>
#include <cuda_bf16.h>

// ---------------- problem constants ----------------
constexpr int kH  = 1024;          // hidden
constexpr int kS  = 2048;          // seq len
constexpr int kB  = 4;             // batch
constexpr int kM  = kB * kS;       // 8192 tokens

// ---------------- GEMM tiling ----------------
constexpr int BM = 128;
constexpr int BN = 128;
constexpr int BK = 8;
constexpr int TM = 8;
constexpr int TN = 8;
constexpr int NT = 256;            // threads per block (16 x 16 microtiles)
constexpr int SPAD = 4;            // smem row padding

// ---------------- scratch (static device globals; no allocs allowed) ----------------
__device__ float g_Q [(size_t)kM * kH];            // 33.5 MB  [token, h]
__device__ float g_K [(size_t)kM * kH];            // 33.5 MB  [token, h]
__device__ float g_Vt[(size_t)kB * kH * kS];       // 33.5 MB  V transposed: [b, h, s]
__device__ float g_Sc[(size_t)kB * kS * kS];       // 67 MB    scores/attn: [b, q, k]

// ---------------------------------------------------------------------------
// NT-GEMM core: C_tile += A_tile * B_tile^T, A row-major [*, lda] (K-major),
// B row-major [*, ldb] (K-major). A/B already offset to this block's first row.
// 128x128 tile, 8-deep K chunks, 8x8 per-thread accumulators.
// ---------------------------------------------------------------------------
__device__ __forceinline__ void gemm_core(const float* __restrict__ A,
                                          const float* __restrict__ B,
                                          int K, int lda, int ldb,
                                          float acc[TM][TN])
{
    __shared__ float As[BK][BM + SPAD];
    __shared__ float Bs[BK][BN + SPAD];

    const int tid = threadIdx.x;
    const int lr  = tid >> 1;            // 0..127 : row within tile to load
    const int lc  = (tid & 1) << 2;      // 0 or 4 : float4 column within K-chunk
    const int tx  = tid & 15;
    const int ty  = tid >> 4;

    const float* Aptr = A + (size_t)lr * lda + lc;
    const float* Bptr = B + (size_t)lr * ldb + lc;

    for (int kk = 0; kk < K; kk += BK) {
        const float4 a4 = *(const float4*)(Aptr + kk);
        const float4 b4 = *(const float4*)(Bptr + kk);
        As[lc + 0][lr] = a4.x; As[lc + 1][lr] = a4.y;
        As[lc + 2][lr] = a4.z; As[lc + 3][lr] = a4.w;
        Bs[lc + 0][lr] = b4.x; Bs[lc + 1][lr] = b4.y;
        Bs[lc + 2][lr] = b4.z; Bs[lc + 3][lr] = b4.w;
        __syncthreads();

        #pragma unroll
        for (int k = 0; k < BK; k++) {
            float am[TM], bn[TN];
            #pragma unroll
            for (int i = 0; i < TM; i++) am[i] = As[k][ty * TM + i];
            #pragma unroll
            for (int j = 0; j < TN; j++) bn[j] = Bs[k][tx * TN + j];
            #pragma unroll
            for (int i = 0; i < TM; i++)
                #pragma unroll
                for (int j = 0; j < TN; j++)
                    acc[i][j] = fmaf(am[i], bn[j], acc[i][j]);
        }
        __syncthreads();
    }
}

// ---------------------------------------------------------------------------
// Kernel 1: fused QKV projection. grid = (kH/BN, kM/BM, 3); z selects Q/K/V.
// V is stored transposed per batch ([b, h, s]) so the attn*V GEMM is also NT.
// ---------------------------------------------------------------------------
__global__ __launch_bounds__(NT, 2)
void qkv_kernel(const float* __restrict__ X,
                const float* __restrict__ Wq, const float* __restrict__ bq,
                const float* __restrict__ Wk, const float* __restrict__ bk,
                const float* __restrict__ Wv, const float* __restrict__ bv)
{
    const int z = blockIdx.z;
    const float* W    = (z == 0) ? Wq : (z == 1) ? Wk : Wv;
    const float* bias = (z == 0) ? bq : (z == 1) ? bk : bv;

    const float* Ablk = X + (size_t)blockIdx.y * BM * kH;
    const float* Bblk = W + (size_t)blockIdx.x * BN * kH;

    float acc[TM][TN];
    #pragma unroll
    for (int i = 0; i < TM; i++)
        #pragma unroll
        for (int j = 0; j < TN; j++) acc[i][j] = 0.0f;

    gemm_core(Ablk, Bblk, kH, kH, kH, acc);

    const int tx = threadIdx.x & 15, ty = threadIdx.x >> 4;
    const int m0 = blockIdx.y * BM + ty * TM;
    const int n0 = blockIdx.x * BN + tx * TN;

    #pragma unroll
    for (int j = 0; j < TN; j++) {
        const int   n  = n0 + j;
        const float bj = __ldg(&bias[n]);
        #pragma unroll
        for (int i = 0; i < TM; i++) {
            const int   m = m0 + i;
            const float v = acc[i][j] + bj;
            if (z == 0) {
                g_Q[(size_t)m * kH + n] = v;
            } else if (z == 1) {
                g_K[(size_t)m * kH + n] = v;
            } else {
                const int b  = m >> 11;          // m / kS
                const int ml = m & (kS - 1);     // m % kS
                g_Vt[((size_t)b * kH + n) * kS + ml] = v;
            }
        }
    }
}

// ---------------------------------------------------------------------------
// Kernel 2: scores = (Q K^T) / sqrt(H). grid = (kS/BN, kS/BM, kB).
// ---------------------------------------------------------------------------
__global__ __launch_bounds__(NT, 2)
void scores_kernel()
{
    const int b = blockIdx.z;
    const float* Ablk = g_Q + ((size_t)b * kS + blockIdx.y * BM) * kH;
    const float* Bblk = g_K + ((size_t)b * kS + blockIdx.x * BN) * kH;

    float acc[TM][TN];
    #pragma unroll
    for (int i = 0; i < TM; i++)
        #pragma unroll
        for (int j = 0; j < TN; j++) acc[i][j] = 0.0f;

    gemm_core(Ablk, Bblk, kH, kH, kH, acc);

    const int tx = threadIdx.x & 15, ty = threadIdx.x >> 4;
    const int m0 = blockIdx.y * BM + ty * TM;
    const int n0 = blockIdx.x * BN + tx * TN;
    const float scale = 0.03125f;  // 1/sqrt(1024)

    #pragma unroll
    for (int i = 0; i < TM; i++)
        #pragma unroll
        for (int j = 0; j < TN; j++)
            g_Sc[((size_t)b * kS + m0 + i) * kS + n0 + j] = acc[i][j] * scale;
}

// ---------------------------------------------------------------------------
// Kernel 3: in-place row softmax over g_Sc. one block per row (2048 cols).
// ---------------------------------------------------------------------------
__global__ __launch_bounds__(256)
void softmax_kernel()
{
    float* row = g_Sc + (size_t)blockIdx.x * kS;
    const int tid = threadIdx.x;

    float v[8];
    float mx = -3.0e38f;
    #pragma unroll
    for (int r = 0; r < 8; r++) {
        v[r] = row[tid + r * 256];
        mx = fmaxf(mx, v[r]);
    }

    __shared__ float red[256];
    red[tid] = mx;
    __syncthreads();
    #pragma unroll
    for (int s2 = 128; s2 > 0; s2 >>= 1) {
        if (tid < s2) red[tid] = fmaxf(red[tid], red[tid + s2]);
        __syncthreads();
    }
    mx = red[0];
    __syncthreads();

    float sum = 0.0f;
    #pragma unroll
    for (int r = 0; r < 8; r++) {
        v[r] = __expf(v[r] - mx);
        sum += v[r];
    }
    red[tid] = sum;
    __syncthreads();
    #pragma unroll
    for (int s2 = 128; s2 > 0; s2 >>= 1) {
        if (tid < s2) red[tid] += red[tid + s2];
        __syncthreads();
    }
    const float inv = 1.0f / red[0];

    #pragma unroll
    for (int r = 0; r < 8; r++)
        row[tid + r * 256] = v[r] * inv;
}

// ---------------------------------------------------------------------------
// Kernel 4: out = attn @ V, via attn [q,k] * Vt[h,k] (NT). grid = (kH/BN, kS/BM, kB).
// ---------------------------------------------------------------------------
__global__ __launch_bounds__(NT, 2)
void out_kernel(float* __restrict__ out)
{
    const int b = blockIdx.z;
    const float* Ablk = g_Sc + ((size_t)b * kS + blockIdx.y * BM) * kS;
    const float* Bblk = g_Vt + ((size_t)b * kH + blockIdx.x * BN) * kS;

    float acc[TM][TN];
    #pragma unroll
    for (int i = 0; i < TM; i++)
        #pragma unroll
        for (int j = 0; j < TN; j++) acc[i][j] = 0.0f;

    gemm_core(Ablk, Bblk, kS, kS, kS, acc);

    const int tx = threadIdx.x & 15, ty = threadIdx.x >> 4;
    const int m0 = blockIdx.y * BM + ty * TM;
    const int n0 = blockIdx.x * BN + tx * TN;

    #pragma unroll
    for (int i = 0; i < TM; i++)
        #pragma unroll
        for (int j = 0; j < TN; j++)
            out[((size_t)b * kS + m0 + i) * kH + n0 + j] = acc[i][j];
}

// ---------------------------------------------------------------------------
// entry point (graph-capturable: kernel launches only, default stream ordering
// carries the QKV -> scores -> softmax -> out dependency chain)
// ---------------------------------------------------------------------------
extern "C" void kernel_launch(void* const* d_in, const int* in_sizes, int n_in,
                              void* d_out, int out_size)
{
    const float* X  = (const float*)d_in[0];
    const float* Wq = (const float*)d_in[1];
    const float* bq = (const float*)d_in[2];
    const float* Wk = (const float*)d_in[3];
    const float* bk = (const float*)d_in[4];
    const float* Wv = (const float*)d_in[5];
    const float* bv = (const float*)d_in[6];
    float* out = (float*)d_out;

    qkv_kernel<<<dim3(kH / BN, kM / BM, 3), NT>>>(X, Wq, bq, Wk, bk, Wv, bv);
    scores_kernel<<<dim3(kS / BN, kS / BM, kB), NT>>>();
    softmax_kernel<<<kB * kS, 256>>>();
    out_kernel<<<dim3(kH / BN, kS / BM, kB), NT>>>(out);
}

// round 8
// speedup vs baseline: 2.1179x; 2.1179x over previous
#include <cuda_runtime.h>
#include <cuda_bf16.h>
#include <cstdint>

// ---------------- problem constants ----------------
constexpr int kH = 1024;
constexpr int kS = 2048;
constexpr int kB = 4;
constexpr int kM = kB * kS;          // 8192

// ---------------- scratch: hi/lo bf16 planes ----------------
__device__ __align__(256) __nv_bfloat16 g_Xh[(size_t)kM * kH];
__device__ __align__(256) __nv_bfloat16 g_Xl[(size_t)kM * kH];
__device__ __align__(256) __nv_bfloat16 g_Wh[(size_t)3 * kH * kH];
__device__ __align__(256) __nv_bfloat16 g_Wl[(size_t)3 * kH * kH];
__device__ __align__(256) __nv_bfloat16 g_Qh[(size_t)kM * kH];
__device__ __align__(256) __nv_bfloat16 g_Ql[(size_t)kM * kH];
__device__ __align__(256) __nv_bfloat16 g_Kh[(size_t)kM * kH];
__device__ __align__(256) __nv_bfloat16 g_Kl[(size_t)kM * kH];
__device__ __align__(256) __nv_bfloat16 g_Vh[(size_t)kB * kH * kS];   // Vt [b][h][s]
__device__ __align__(256) __nv_bfloat16 g_Vl[(size_t)kB * kH * kS];
__device__ __align__(256) float         g_Sc[(size_t)kB * kS * kS];
__device__ __align__(256) __nv_bfloat16 g_Ah[(size_t)kB * kS * kS];   // attn
__device__ __align__(256) __nv_bfloat16 g_Al[(size_t)kB * kS * kS];

// ---------------- low-level helpers (all sm_80-portable PTX) ----------------
__device__ __forceinline__ uint32_t smem_u32(const void* p) {
    uint32_t a;
    asm("{ .reg .u64 t; cvta.to.shared.u64 t, %1; cvt.u32.u64 %0, t; }" : "=r"(a) : "l"(p));
    return a;
}

#define CP_ASYNC16(dst, src) \
    asm volatile("cp.async.cg.shared.global [%0], [%1], 16;" :: "r"(dst), "l"(src) : "memory")
#define CP_COMMIT() asm volatile("cp.async.commit_group;" ::: "memory")
#define CP_WAIT1()  asm volatile("cp.async.wait_group 1;" ::: "memory")

__device__ __forceinline__ void ldsm_x4(uint32_t* r, uint32_t addr) {
    asm volatile("ldmatrix.sync.aligned.m8n8.x4.shared.b16 {%0,%1,%2,%3}, [%4];"
                 : "=r"(r[0]), "=r"(r[1]), "=r"(r[2]), "=r"(r[3]) : "r"(addr));
}

__device__ __forceinline__ void mma16816(float* c, const uint32_t* a, const uint32_t* b) {
    asm volatile(
        "mma.sync.aligned.m16n8k16.row.col.f32.bf16.bf16.f32 "
        "{%0,%1,%2,%3}, {%4,%5,%6,%7}, {%8,%9}, {%0,%1,%2,%3};"
        : "+f"(c[0]), "+f"(c[1]), "+f"(c[2]), "+f"(c[3])
        : "r"(a[0]), "r"(a[1]), "r"(a[2]), "r"(a[3]), "r"(b[0]), "r"(b[1]));
}

// smem tile layout: 128 logical rows x 32 bf16 (64B), packed as 64 phys rows x 128B,
// 16B chunks XOR-swizzled so ldmatrix row-groups of 8 are bank-conflict-free.
__device__ __forceinline__ uint32_t phys(int m, int kc) {
    return (uint32_t)(((m & 63) << 7) | (((((m >> 6) << 2) | kc) ^ (m & 7)) << 4));
}

__device__ __forceinline__ void split2(float x, __nv_bfloat16& h, __nv_bfloat16& l) {
    h = __float2bfloat16(x);
    l = __float2bfloat16(x - __bfloat162float(h));
}
__device__ __forceinline__ uint32_t pack_bf2(__nv_bfloat16 a, __nv_bfloat16 b) {
    uint16_t ua = *(uint16_t*)&a, ub = *(uint16_t*)&b;
    return (uint32_t)ua | ((uint32_t)ub << 16);
}

// stage layout: Ah @0, Al @8192, Bh @16384, Bl @24576; stage stride 32768; 2 stages.
constexpr int SM_AL = 8192, SM_BH = 16384, SM_BL = 24576;
constexpr int STAGE = 32768;
constexpr int SMEM_BYTES = 2 * STAGE;

// ---------------------------------------------------------------------------
// mainloop: acc[2][4][4] = (Ah+Al)[128,K] x (Bh+Bl)[128,K]^T (3-term split),
// 512 threads, warp grid 4x4, warp tile 32x32.
// ---------------------------------------------------------------------------
__device__ __forceinline__ void run_mainloop(
    float acc[2][4][4],
    const __nv_bfloat16* __restrict__ Ah, const __nv_bfloat16* __restrict__ Al,
    const __nv_bfloat16* __restrict__ Bh, const __nv_bfloat16* __restrict__ Bl,
    int lda, int ldb, int niter, uint32_t sbase)
{
    const int tid = threadIdx.x, lane = tid & 31, wid = tid >> 5;
    const int wm = wid >> 2, wn = wid & 3;

    #pragma unroll
    for (int i = 0; i < 2; i++)
        #pragma unroll
        for (int j = 0; j < 4; j++)
            #pragma unroll
            for (int c = 0; c < 4; c++) acc[i][j][c] = 0.0f;

    // cp.async slot: thread -> one 16B chunk per operand tile
    const int m_ld = tid >> 2, kc_ld = tid & 3;
    const uint32_t sw_ld = phys(m_ld, kc_ld);
    const size_t a_src0 = (size_t)m_ld * lda + kc_ld * 8;
    const size_t b_src0 = (size_t)m_ld * ldb + kc_ld * 8;

    // precomputed ldmatrix swizzled offsets
    uint32_t a_off[2][2], b_off[2][2];
    #pragma unroll
    for (int i = 0; i < 2; i++)
        #pragma unroll
        for (int ks = 0; ks < 2; ks++) {
            const int am  = wm * 32 + i * 16 + (lane & 15);
            const int akc = ks * 2 + (lane >> 4);
            a_off[i][ks] = phys(am, akc);
            const int bn  = wn * 32 + i * 16 + ((lane >> 4) << 3) + (lane & 7);
            const int bkc = ks * 2 + ((lane >> 3) & 1);
            b_off[i][ks] = phys(bn, bkc);
        }

    auto load_stage = [&](int it) {
        const uint32_t st = sbase + (uint32_t)(it & 1) * STAGE;
        const size_t ao = a_src0 + (size_t)it * 32;
        const size_t bo = b_src0 + (size_t)it * 32;
        CP_ASYNC16(st +         sw_ld, Ah + ao);
        CP_ASYNC16(st + SM_AL + sw_ld, Al + ao);
        CP_ASYNC16(st + SM_BH + sw_ld, Bh + bo);
        CP_ASYNC16(st + SM_BL + sw_ld, Bl + bo);
    };

    load_stage(0); CP_COMMIT();
    load_stage(1); CP_COMMIT();

    for (int it = 0; it < niter; ++it) {
        CP_WAIT1();
        __syncthreads();
        const uint32_t st = sbase + (uint32_t)(it & 1) * STAGE;

        #pragma unroll
        for (int ks = 0; ks < 2; ++ks) {
            uint32_t ah[2][4], al[2][4], bh[2][4], bl[2][4];
            ldsm_x4(ah[0], st +          a_off[0][ks]);
            ldsm_x4(ah[1], st +          a_off[1][ks]);
            ldsm_x4(al[0], st + SM_AL + a_off[0][ks]);
            ldsm_x4(al[1], st + SM_AL + a_off[1][ks]);
            ldsm_x4(bh[0], st + SM_BH + b_off[0][ks]);
            ldsm_x4(bh[1], st + SM_BH + b_off[1][ks]);
            ldsm_x4(bl[0], st + SM_BL + b_off[0][ks]);
            ldsm_x4(bl[1], st + SM_BL + b_off[1][ks]);
            #pragma unroll
            for (int i = 0; i < 2; i++)
                #pragma unroll
                for (int j = 0; j < 4; j++) {
                    const uint32_t* bhp = &bh[j >> 1][(j & 1) * 2];
                    const uint32_t* blp = &bl[j >> 1][(j & 1) * 2];
                    mma16816(acc[i][j], ah[i], bhp);   // Ah*Bh
                    mma16816(acc[i][j], al[i], bhp);   // Al*Bh
                    mma16816(acc[i][j], ah[i], blp);   // Ah*Bl
                }
        }
        __syncthreads();
        if (it + 2 < niter) load_stage(it + 2);
        CP_COMMIT();
    }
}

// ---------------- kernel 1: QKV projection ----------------
__global__ __launch_bounds__(512, 1)
void qkv_gemm(const float* __restrict__ bq, const float* __restrict__ bk,
              const float* __restrict__ bv)
{
    extern __shared__ char smem[];
    const int z = blockIdx.z;
    const size_t rowb = (size_t)blockIdx.y * 128;
    const size_t colb = (size_t)blockIdx.x * 128;
    float acc[2][4][4];
    run_mainloop(acc,
                 g_Xh + rowb * kH, g_Xl + rowb * kH,
                 g_Wh + ((size_t)z * kH + colb) * kH,
                 g_Wl + ((size_t)z * kH + colb) * kH,
                 kH, kH, kH / 32, smem_u32(smem));

    const float* bias = (z == 0) ? bq : (z == 1) ? bk : bv;
    const int tid = threadIdx.x, lane = tid & 31, wid = tid >> 5;
    const int wm = wid >> 2, wn = wid & 3;
    const int mloc0 = wm * 32 + (lane >> 2);
    const int nloc0 = wn * 32 + (lane & 3) * 2;

    #pragma unroll
    for (int i = 0; i < 2; i++)
        #pragma unroll
        for (int j = 0; j < 4; j++) {
            const int n = (int)colb + nloc0 + j * 8;
            const float2 bb = *(const float2*)&bias[n];
            #pragma unroll
            for (int half = 0; half < 2; half++) {
                const int m = (int)rowb + mloc0 + i * 16 + half * 8;
                const float v0 = acc[i][j][half * 2 + 0] + bb.x;
                const float v1 = acc[i][j][half * 2 + 1] + bb.y;
                __nv_bfloat16 h0, l0, h1, l1;
                split2(v0, h0, l0); split2(v1, h1, l1);
                if (z == 0) {
                    *(uint32_t*)&g_Qh[(size_t)m * kH + n] = pack_bf2(h0, h1);
                    *(uint32_t*)&g_Ql[(size_t)m * kH + n] = pack_bf2(l0, l1);
                } else if (z == 1) {
                    *(uint32_t*)&g_Kh[(size_t)m * kH + n] = pack_bf2(h0, h1);
                    *(uint32_t*)&g_Kl[(size_t)m * kH + n] = pack_bf2(l0, l1);
                } else {
                    const int b = m >> 11, s = m & (kS - 1);
                    const size_t base = ((size_t)b * kH + n) * kS + s;
                    g_Vh[base] = h0; g_Vh[base + kS] = h1;
                    g_Vl[base] = l0; g_Vl[base + kS] = l1;
                }
            }
        }
}

// ---------------- kernel 2: scores = QK^T / 32 ----------------
__global__ __launch_bounds__(512, 1)
void scores_gemm()
{
    extern __shared__ char smem[];
    const int b = blockIdx.z;
    const size_t rowb = (size_t)b * kS + blockIdx.y * 128;
    const size_t colb = (size_t)b * kS + blockIdx.x * 128;
    float acc[2][4][4];
    run_mainloop(acc, g_Qh + rowb * kH, g_Ql + rowb * kH,
                      g_Kh + colb * kH, g_Kl + colb * kH,
                 kH, kH, kH / 32, smem_u32(smem));

    const int tid = threadIdx.x, lane = tid & 31, wid = tid >> 5;
    const int wm = wid >> 2, wn = wid & 3;
    const int mloc0 = blockIdx.y * 128 + wm * 32 + (lane >> 2);
    const int nloc0 = blockIdx.x * 128 + wn * 32 + (lane & 3) * 2;

    #pragma unroll
    for (int i = 0; i < 2; i++)
        #pragma unroll
        for (int j = 0; j < 4; j++) {
            const int n = nloc0 + j * 8;
            #pragma unroll
            for (int half = 0; half < 2; half++) {
                const int m = mloc0 + i * 16 + half * 8;
                float2 v = { acc[i][j][half * 2 + 0] * 0.03125f,
                             acc[i][j][half * 2 + 1] * 0.03125f };
                *(float2*)&g_Sc[((size_t)b * kS + m) * kS + n] = v;
            }
        }
}

// ---------------- kernel 3: softmax + split to bf16 planes ----------------
__global__ __launch_bounds__(256)
void softmax_kernel()
{
    const size_t row = blockIdx.x;
    const float* src = g_Sc + row * kS;
    __nv_bfloat16* dh = g_Ah + row * kS;
    __nv_bfloat16* dl = g_Al + row * kS;
    const int tid = threadIdx.x;

    float v[8];
    float mx = -3.0e38f;
    #pragma unroll
    for (int r = 0; r < 8; r++) { v[r] = src[tid + r * 256]; mx = fmaxf(mx, v[r]); }

    __shared__ float red[256];
    red[tid] = mx; __syncthreads();
    #pragma unroll
    for (int s2 = 128; s2 > 0; s2 >>= 1) {
        if (tid < s2) red[tid] = fmaxf(red[tid], red[tid + s2]);
        __syncthreads();
    }
    mx = red[0]; __syncthreads();

    float sum = 0.0f;
    #pragma unroll
    for (int r = 0; r < 8; r++) { v[r] = __expf(v[r] - mx); sum += v[r]; }
    red[tid] = sum; __syncthreads();
    #pragma unroll
    for (int s2 = 128; s2 > 0; s2 >>= 1) {
        if (tid < s2) red[tid] += red[tid + s2];
        __syncthreads();
    }
    const float inv = 1.0f / red[0];

    #pragma unroll
    for (int r = 0; r < 8; r++) {
        const int c = tid + r * 256;
        __nv_bfloat16 h, l; split2(v[r] * inv, h, l);
        dh[c] = h;
        dl[c] = l;
    }
}

// ---------------- kernel 4: out = attn @ V ----------------
__global__ __launch_bounds__(512, 1)
void out_gemm(float* __restrict__ out)
{
    extern __shared__ char smem[];
    const int b = blockIdx.z;
    const size_t rowb = (size_t)b * kS + blockIdx.y * 128;
    const size_t colb = (size_t)b * kH + blockIdx.x * 128;
    float acc[2][4][4];
    run_mainloop(acc, g_Ah + rowb * kS, g_Al + rowb * kS,
                      g_Vh + colb * kS, g_Vl + colb * kS,
                 kS, kS, kS / 32, smem_u32(smem));

    const int tid = threadIdx.x, lane = tid & 31, wid = tid >> 5;
    const int wm = wid >> 2, wn = wid & 3;
    const int mloc0 = blockIdx.y * 128 + wm * 32 + (lane >> 2);
    const int nloc0 = blockIdx.x * 128 + wn * 32 + (lane & 3) * 2;

    #pragma unroll
    for (int i = 0; i < 2; i++)
        #pragma unroll
        for (int j = 0; j < 4; j++) {
            const int n = nloc0 + j * 8;
            #pragma unroll
            for (int half = 0; half < 2; half++) {
                const int m = mloc0 + i * 16 + half * 8;
                float2 v = { acc[i][j][half * 2 + 0], acc[i][j][half * 2 + 1] };
                *(float2*)&out[((size_t)b * kS + m) * kH + n] = v;
            }
        }
}

// ---------------- conversion kernels ----------------
__global__ __launch_bounds__(256)
void convX_kernel(const float* __restrict__ X)
{
    const size_t i = ((size_t)blockIdx.x * 256 + threadIdx.x) * 4;
    const float4 x = *(const float4*)&X[i];
    __nv_bfloat16 h0, l0, h1, l1, h2, l2, h3, l3;
    split2(x.x, h0, l0); split2(x.y, h1, l1);
    split2(x.z, h2, l2); split2(x.w, h3, l3);
    uint2 ph = { pack_bf2(h0, h1), pack_bf2(h2, h3) };
    uint2 pl = { pack_bf2(l0, l1), pack_bf2(l2, l3) };
    *(uint2*)&g_Xh[i] = ph;
    *(uint2*)&g_Xl[i] = pl;
}

__global__ __launch_bounds__(256)
void convW_kernel(const float* __restrict__ Wq, const float* __restrict__ Wk,
                  const float* __restrict__ Wv)
{
    const size_t i = ((size_t)blockIdx.x * 256 + threadIdx.x) * 4;
    const int z = (int)(i >> 20);                       // kH*kH = 2^20
    const size_t r = i & ((size_t)kH * kH - 1);
    const float* W = (z == 0) ? Wq : (z == 1) ? Wk : Wv;
    const float4 x = *(const float4*)&W[r];
    __nv_bfloat16 h0, l0, h1, l1, h2, l2, h3, l3;
    split2(x.x, h0, l0); split2(x.y, h1, l1);
    split2(x.z, h2, l2); split2(x.w, h3, l3);
    uint2 ph = { pack_bf2(h0, h1), pack_bf2(h2, h3) };
    uint2 pl = { pack_bf2(l0, l1), pack_bf2(l2, l3) };
    *(uint2*)&g_Wh[i] = ph;
    *(uint2*)&g_Wl[i] = pl;
}

// ---------------- entry point ----------------
extern "C" void kernel_launch(void* const* d_in, const int* in_sizes, int n_in,
                              void* d_out, int out_size)
{
    const float* X  = (const float*)d_in[0];
    const float* Wq = (const float*)d_in[1];
    const float* bq = (const float*)d_in[2];
    const float* Wk = (const float*)d_in[3];
    const float* bk = (const float*)d_in[4];
    const float* Wv = (const float*)d_in[5];
    const float* bv = (const float*)d_in[6];
    float* out = (float*)d_out;

    static bool attr_done = false;
    if (!attr_done) {
        cudaFuncSetAttribute(qkv_gemm,    cudaFuncAttributeMaxDynamicSharedMemorySize, SMEM_BYTES);
        cudaFuncSetAttribute(scores_gemm, cudaFuncAttributeMaxDynamicSharedMemorySize, SMEM_BYTES);
        cudaFuncSetAttribute(out_gemm,    cudaFuncAttributeMaxDynamicSharedMemorySize, SMEM_BYTES);
        attr_done = true;
    }

    convX_kernel<<<(int)((size_t)kM * kH / 4 / 256), 256>>>(X);
    convW_kernel<<<(int)((size_t)3 * kH * kH / 4 / 256), 256>>>(Wq, Wk, Wv);
    qkv_gemm   <<<dim3(kH / 128, kM / 128, 3), 512, SMEM_BYTES>>>(bq, bk, bv);
    scores_gemm<<<dim3(kS / 128, kS / 128, kB), 512, SMEM_BYTES>>>();
    softmax_kernel<<<kM, 256>>>();
    out_gemm   <<<dim3(kH / 128, kS / 128, kB), 512, SMEM_BYTES>>>(out);
}

// round 9
// speedup vs baseline: 3.7794x; 1.7845x over previous
#include <cuda_runtime.h>
#include <cuda_bf16.h>
#include <cstdint>

// ---------------- problem constants ----------------
constexpr int kH = 1024;
constexpr int kS = 2048;
constexpr int kB = 4;
constexpr int kM = kB * kS;          // 8192

// ---------------- scratch (tf32-rounded fp32 operands) ----------------
__device__ __align__(256) float g_X [(size_t)kM * kH];          // 33.5 MB
__device__ __align__(256) float g_W [(size_t)3 * kH * kH];      // 12.6 MB
__device__ __align__(256) float g_Q [(size_t)kM * kH];
__device__ __align__(256) float g_K [(size_t)kM * kH];
__device__ __align__(256) float g_Vt[(size_t)kB * kH * kS];     // [b][h][s]
__device__ __align__(256) float g_Sc[(size_t)kB * kS * kS];     // scores -> attn (in-place)

// ---------------- helpers ----------------
__device__ __forceinline__ uint32_t smem_u32(const void* p) {
    uint32_t a;
    asm("{ .reg .u64 t; cvta.to.shared.u64 t, %1; cvt.u32.u64 %0, t; }" : "=r"(a) : "l"(p));
    return a;
}
__device__ __forceinline__ float rna_tf32(float x) {
    uint32_t o;
    asm("cvt.rna.tf32.f32 %0, %1;" : "=r"(o) : "f"(x));
    return __uint_as_float(o);
}

#define CP_ASYNC16(dst, src) \
    asm volatile("cp.async.cg.shared.global [%0], [%1], 16;" :: "r"(dst), "l"(src) : "memory")
#define CP_COMMIT() asm volatile("cp.async.commit_group;" ::: "memory")
#define CP_WAIT1()  asm volatile("cp.async.wait_group 1;" ::: "memory")

__device__ __forceinline__ void mma_tf32(float* c, const uint32_t* a, const uint32_t* b) {
    asm volatile(
        "mma.sync.aligned.m16n8k8.row.col.f32.tf32.tf32.f32 "
        "{%0,%1,%2,%3}, {%4,%5,%6,%7}, {%8,%9}, {%0,%1,%2,%3};"
        : "+f"(c[0]), "+f"(c[1]), "+f"(c[2]), "+f"(c[3])
        : "r"(a[0]), "r"(a[1]), "r"(a[2]), "r"(a[3]), "r"(b[0]), "r"(b[1]));
}

// ---------------- tiling ----------------
// CTA 128x128, 8 warps in 4(m) x 2(n), warp tile 32x64, BK=32.
// smem tile: 128 rows x 36 floats (32 data + 4 pad), row = 144 B (16B aligned).
constexpr int ROWF  = 36;
constexpr int ROWB  = 144;
constexpr int SM_B  = 128 * ROWB;        // 18432: B tile follows A tile
constexpr int STAGE = 2 * 128 * ROWB;    // 36864
constexpr int SMEM_BYTES = 2 * STAGE;    // 73728

// ---------------------------------------------------------------------------
// mainloop: acc[2][8][4] += A[128,K] x B[128,K]^T (tf32, NT), 256 threads.
// ---------------------------------------------------------------------------
__device__ __forceinline__ void run_mainloop(
    float acc[2][8][4],
    const float* __restrict__ A, const float* __restrict__ B,
    int lda, int ldb, int niter, char* smem)
{
    const int tid = threadIdx.x, lane = tid & 31, wid = tid >> 5;
    const int wm = wid >> 1, wn = wid & 1;
    const uint32_t sbase = smem_u32(smem);

    #pragma unroll
    for (int i = 0; i < 2; i++)
        #pragma unroll
        for (int j = 0; j < 8; j++)
            #pragma unroll
            for (int c = 0; c < 4; c++) acc[i][j][c] = 0.0f;

    // cp.async slots: per operand 1024 16B chunks (128 rows x 8 chunks), 4/thread.
    const int r_ld = tid >> 1;              // rows: 2 threads per row... no:
    // chunk id = tid + t*256 ; r = ch>>3, c = ch&7
    auto load_stage = [&](int it) {
        const uint32_t st = sbase + (uint32_t)(it & 1) * STAGE;
        const int k0 = it * 32;
        #pragma unroll
        for (int t = 0; t < 4; t++) {
            const int ch = tid + t * 256;
            const int r = ch >> 3, c = ch & 7;
            CP_ASYNC16(st +        (uint32_t)(r * ROWB + c * 16), A + (size_t)r * lda + k0 + c * 4);
            CP_ASYNC16(st + SM_B + (uint32_t)(r * ROWB + c * 16), B + (size_t)r * ldb + k0 + c * 4);
        }
    };

    // fragment byte offsets (within stage)
    uint32_t a_base[2], b_base[8];
    #pragma unroll
    for (int i = 0; i < 2; i++)
        a_base[i] = (uint32_t)(((wm * 32 + i * 16 + (lane >> 2)) * ROWF + (lane & 3)) * 4);
    #pragma unroll
    for (int j = 0; j < 8; j++)
        b_base[j] = (uint32_t)(SM_B + ((wn * 64 + j * 8 + (lane >> 2)) * ROWF + (lane & 3)) * 4);

    load_stage(0); CP_COMMIT();
    load_stage(1); CP_COMMIT();

    for (int it = 0; it < niter; ++it) {
        CP_WAIT1();
        __syncthreads();
        const char* st = smem + (it & 1) * STAGE;

        #pragma unroll
        for (int ks = 0; ks < 4; ++ks) {
            const uint32_t ko = ks * 32;   // 8 floats per k8 step
            uint32_t a[2][4], b[8][2];
            #pragma unroll
            for (int i = 0; i < 2; i++) {
                const char* p = st + a_base[i] + ko;
                a[i][0] = *(const uint32_t*)(p);
                a[i][1] = *(const uint32_t*)(p + 8 * ROWB);    // row + 8
                a[i][2] = *(const uint32_t*)(p + 16);          // k + 4
                a[i][3] = *(const uint32_t*)(p + 8 * ROWB + 16);
            }
            #pragma unroll
            for (int j = 0; j < 8; j++) {
                const char* p = st + b_base[j] + ko;
                b[j][0] = *(const uint32_t*)(p);
                b[j][1] = *(const uint32_t*)(p + 16);          // k + 4
            }
            #pragma unroll
            for (int i = 0; i < 2; i++)
                #pragma unroll
                for (int j = 0; j < 8; j++)
                    mma_tf32(acc[i][j], a[i], b[j]);
        }
        __syncthreads();
        if (it + 2 < niter) load_stage(it + 2);
        CP_COMMIT();
    }
}

// epilogue index helpers: warp 4x2, warp tile 32x64
// c0,c1 -> (m, n), (m, n+1); c2,c3 -> (m+8, n), (m+8, n+1); n = wn*64 + j*8 + (lane&3)*2
// m = wm*32 + i*16 + lane>>2

// ---------------- kernel 1: QKV projection ----------------
__global__ __launch_bounds__(256, 2)
void qkv_gemm(const float* __restrict__ bq, const float* __restrict__ bk,
              const float* __restrict__ bv)
{
    extern __shared__ char smem[];
    const int z = blockIdx.z;
    const size_t rowb = (size_t)blockIdx.y * 128;
    const size_t colb = (size_t)blockIdx.x * 128;
    float acc[2][8][4];
    run_mainloop(acc, g_X + rowb * kH,
                      g_W + ((size_t)z * kH + colb) * kH,
                 kH, kH, kH / 32, smem);

    const float* bias = (z == 0) ? bq : (z == 1) ? bk : bv;
    const int tid = threadIdx.x, lane = tid & 31, wid = tid >> 5;
    const int wm = wid >> 1, wn = wid & 1;
    const int mloc0 = (int)rowb + wm * 32 + (lane >> 2);
    const int nloc0 = (int)colb + wn * 64 + (lane & 3) * 2;

    #pragma unroll
    for (int i = 0; i < 2; i++)
        #pragma unroll
        for (int j = 0; j < 8; j++) {
            const int n = nloc0 + j * 8;
            const float2 bb = *(const float2*)&bias[n];
            #pragma unroll
            for (int half = 0; half < 2; half++) {
                const int m = mloc0 + i * 16 + half * 8;
                const float v0 = rna_tf32(acc[i][j][half * 2 + 0] + bb.x);
                const float v1 = rna_tf32(acc[i][j][half * 2 + 1] + bb.y);
                if (z == 0) {
                    *(float2*)&g_Q[(size_t)m * kH + n] = make_float2(v0, v1);
                } else if (z == 1) {
                    *(float2*)&g_K[(size_t)m * kH + n] = make_float2(v0, v1);
                } else {
                    const int b = m >> 11, s = m & (kS - 1);
                    const size_t base = ((size_t)b * kH + n) * kS + s;
                    g_Vt[base]      = v0;
                    g_Vt[base + kS] = v1;
                }
            }
        }
}

// ---------------- kernel 2: scores = QK^T / 32 (fp32 out, no rounding) ----------------
__global__ __launch_bounds__(256, 2)
void scores_gemm()
{
    extern __shared__ char smem[];
    const int b = blockIdx.z;
    const size_t rowb = (size_t)b * kS + blockIdx.y * 128;
    const size_t colb = (size_t)b * kS + blockIdx.x * 128;
    float acc[2][8][4];
    run_mainloop(acc, g_Q + rowb * kH, g_K + colb * kH, kH, kH, kH / 32, smem);

    const int tid = threadIdx.x, lane = tid & 31, wid = tid >> 5;
    const int wm = wid >> 1, wn = wid & 1;
    const int mloc0 = blockIdx.y * 128 + wm * 32 + (lane >> 2);
    const int nloc0 = blockIdx.x * 128 + wn * 64 + (lane & 3) * 2;

    #pragma unroll
    for (int i = 0; i < 2; i++)
        #pragma unroll
        for (int j = 0; j < 8; j++) {
            const int n = nloc0 + j * 8;
            #pragma unroll
            for (int half = 0; half < 2; half++) {
                const int m = mloc0 + i * 16 + half * 8;
                float2 v = { acc[i][j][half * 2 + 0] * 0.03125f,
                             acc[i][j][half * 2 + 1] * 0.03125f };
                *(float2*)&g_Sc[((size_t)b * kS + m) * kS + n] = v;
            }
        }
}

// ---------------- kernel 3: softmax in place + tf32 rounding ----------------
__global__ __launch_bounds__(256)
void softmax_kernel()
{
    float* row = g_Sc + (size_t)blockIdx.x * kS;
    const int tid = threadIdx.x;

    float v[8];
    float mx = -3.0e38f;
    #pragma unroll
    for (int r = 0; r < 8; r++) { v[r] = row[tid + r * 256]; mx = fmaxf(mx, v[r]); }

    __shared__ float red[256];
    red[tid] = mx; __syncthreads();
    #pragma unroll
    for (int s2 = 128; s2 > 0; s2 >>= 1) {
        if (tid < s2) red[tid] = fmaxf(red[tid], red[tid + s2]);
        __syncthreads();
    }
    mx = red[0]; __syncthreads();

    float sum = 0.0f;
    #pragma unroll
    for (int r = 0; r < 8; r++) { v[r] = __expf(v[r] - mx); sum += v[r]; }
    red[tid] = sum; __syncthreads();
    #pragma unroll
    for (int s2 = 128; s2 > 0; s2 >>= 1) {
        if (tid < s2) red[tid] += red[tid + s2];
        __syncthreads();
    }
    const float inv = 1.0f / red[0];

    #pragma unroll
    for (int r = 0; r < 8; r++)
        row[tid + r * 256] = rna_tf32(v[r] * inv);
}

// ---------------- kernel 4: out = attn @ V ----------------
__global__ __launch_bounds__(256, 2)
void out_gemm(float* __restrict__ out)
{
    extern __shared__ char smem[];
    const int b = blockIdx.z;
    const size_t rowb = (size_t)b * kS + blockIdx.y * 128;
    const size_t colb = (size_t)b * kH + blockIdx.x * 128;
    float acc[2][8][4];
    run_mainloop(acc, g_Sc + rowb * kS, g_Vt + colb * kS, kS, kS, kS / 32, smem);

    const int tid = threadIdx.x, lane = tid & 31, wid = tid >> 5;
    const int wm = wid >> 1, wn = wid & 1;
    const int mloc0 = blockIdx.y * 128 + wm * 32 + (lane >> 2);
    const int nloc0 = blockIdx.x * 128 + wn * 64 + (lane & 3) * 2;

    #pragma unroll
    for (int i = 0; i < 2; i++)
        #pragma unroll
        for (int j = 0; j < 8; j++) {
            const int n = nloc0 + j * 8;
            #pragma unroll
            for (int half = 0; half < 2; half++) {
                const int m = mloc0 + i * 16 + half * 8;
                float2 v = { acc[i][j][half * 2 + 0], acc[i][j][half * 2 + 1] };
                *(float2*)&out[((size_t)b * kS + m) * kH + n] = v;
            }
        }
}

// ---------------- conversion prepass: fp32 -> tf32-rounded fp32 ----------------
__global__ __launch_bounds__(256)
void convX_kernel(const float* __restrict__ X)
{
    const size_t i = ((size_t)blockIdx.x * 256 + threadIdx.x) * 4;
    float4 x = *(const float4*)&X[i];
    x.x = rna_tf32(x.x); x.y = rna_tf32(x.y);
    x.z = rna_tf32(x.z); x.w = rna_tf32(x.w);
    *(float4*)&g_X[i] = x;
}

__global__ __launch_bounds__(256)
void convW_kernel(const float* __restrict__ Wq, const float* __restrict__ Wk,
                  const float* __restrict__ Wv)
{
    const size_t i = ((size_t)blockIdx.x * 256 + threadIdx.x) * 4;
    const int z = (int)(i >> 20);                    // kH*kH = 2^20
    const size_t r = i & ((size_t)kH * kH - 1);
    const float* W = (z == 0) ? Wq : (z == 1) ? Wk : Wv;
    float4 x = *(const float4*)&W[r];
    x.x = rna_tf32(x.x); x.y = rna_tf32(x.y);
    x.z = rna_tf32(x.z); x.w = rna_tf32(x.w);
    *(float4*)&g_W[i] = x;
}

// ---------------- entry point ----------------
extern "C" void kernel_launch(void* const* d_in, const int* in_sizes, int n_in,
                              void* d_out, int out_size)
{
    const float* X  = (const float*)d_in[0];
    const float* Wq = (const float*)d_in[1];
    const float* bq = (const float*)d_in[2];
    const float* Wk = (const float*)d_in[3];
    const float* bk = (const float*)d_in[4];
    const float* Wv = (const float*)d_in[5];
    const float* bv = (const float*)d_in[6];
    float* out = (float*)d_out;

    static bool attr_done = false;
    if (!attr_done) {
        cudaFuncSetAttribute(qkv_gemm,    cudaFuncAttributeMaxDynamicSharedMemorySize, SMEM_BYTES);
        cudaFuncSetAttribute(scores_gemm, cudaFuncAttributeMaxDynamicSharedMemorySize, SMEM_BYTES);
        cudaFuncSetAttribute(out_gemm,    cudaFuncAttributeMaxDynamicSharedMemorySize, SMEM_BYTES);
        attr_done = true;
    }

    convX_kernel<<<(int)((size_t)kM * kH / 4 / 256), 256>>>(X);
    convW_kernel<<<(int)((size_t)3 * kH * kH / 4 / 256), 256>>>(Wq, Wk, Wv);
    qkv_gemm   <<<dim3(kH / 128, kM / 128, 3), 256, SMEM_BYTES>>>(bq, bk, bv);
    scores_gemm<<<dim3(kS / 128, kS / 128, kB), 256, SMEM_BYTES>>>();
    softmax_kernel<<<kM, 256>>>();
    out_gemm   <<<dim3(kH / 128, kS / 128, kB), 256, SMEM_BYTES>>>(out);
}

// round 11
// speedup vs baseline: 3.8270x; 1.0126x over previous
#include <cuda_runtime.h>
#include <cuda_bf16.h>
#include <cstdint>

// ---------------- problem constants ----------------
constexpr int kH = 1024;
constexpr int kS = 2048;
constexpr int kB = 4;
constexpr int kM = kB * kS;          // 8192

// ---------------- scratch (tf32-rounded fp32 operands) ----------------
__device__ __align__(256) float g_X [(size_t)kM * kH];
__device__ __align__(256) float g_W [(size_t)3 * kH * kH];
__device__ __align__(256) float g_Q [(size_t)kM * kH];
__device__ __align__(256) float g_K [(size_t)kM * kH];
__device__ __align__(256) float g_Vt[(size_t)kB * kH * kS];     // [b][h][s]
__device__ __align__(256) float g_Sc[(size_t)kB * kS * kS];     // scores -> attn (in-place)

// ---------------- helpers ----------------
__device__ __forceinline__ uint32_t smem_u32(const void* p) {
    uint32_t a;
    asm("{ .reg .u64 t; cvta.to.shared.u64 t, %1; cvt.u32.u64 %0, t; }" : "=r"(a) : "l"(p));
    return a;
}
__device__ __forceinline__ float rna_tf32(float x) {
    uint32_t o;
    asm("cvt.rna.tf32.f32 %0, %1;" : "=r"(o) : "f"(x));
    return __uint_as_float(o);
}

#define CP_ASYNC16(dst, src) \
    asm volatile("cp.async.cg.shared.global [%0], [%1], 16;" :: "r"(dst), "l"(src) : "memory")
#define CP_COMMIT() asm volatile("cp.async.commit_group;" ::: "memory")
#define CP_WAIT1()  asm volatile("cp.async.wait_group 1;" ::: "memory")

__device__ __forceinline__ void mma_tf32(float* c, const uint32_t* a, const uint32_t* b) {
    asm volatile(
        "mma.sync.aligned.m16n8k8.row.col.f32.tf32.tf32.f32 "
        "{%0,%1,%2,%3}, {%4,%5,%6,%7}, {%8,%9}, {%0,%1,%2,%3};"
        : "+f"(c[0]), "+f"(c[1]), "+f"(c[2]), "+f"(c[3])
        : "r"(a[0]), "r"(a[1]), "r"(a[2]), "r"(a[3]), "r"(b[0]), "r"(b[1]));
}

// ---------------- tiling ----------------
// CTA 128x128, 8 warps 4(m) x 2(n), warp tile 32x64, BK=32.
// smem tile row: 32 data floats + 4 pad = 36 floats = 144 B.
// 3-stage pipeline: stage holds A(128x36f) + B(128x36f) = 36,864 B.
constexpr int ROWF  = 36;
constexpr int ROWB  = 144;
constexpr int SM_B  = 128 * ROWB;        // 18432
constexpr int STAGE = 2 * 128 * ROWB;    // 36864
constexpr int NSTG  = 3;
constexpr int SMEM_BYTES = NSTG * STAGE; // 110592 (2 CTAs/SM = 221 KB)

// ---------------------------------------------------------------------------
// mainloop: acc[2][8][4] += A[128,K] x B[128,K]^T (tf32, NT), 256 threads.
// 3-stage cp.async pipeline, single __syncthreads per iteration, loads for
// stage it+2 issued BEFORE the compute of stage it.
// ---------------------------------------------------------------------------
__device__ __forceinline__ void run_mainloop(
    float acc[2][8][4],
    const float* __restrict__ A, const float* __restrict__ B,
    int lda, int ldb, int niter, char* smem)
{
    const int tid = threadIdx.x, lane = tid & 31, wid = tid >> 5;
    const int wm = wid >> 1, wn = wid & 1;
    const uint32_t sbase = smem_u32(smem);

    #pragma unroll
    for (int i = 0; i < 2; i++)
        #pragma unroll
        for (int j = 0; j < 8; j++)
            #pragma unroll
            for (int c = 0; c < 4; c++) acc[i][j][c] = 0.0f;

    // cp.async: per operand 1024 16B chunks (128 rows x 8), 4 chunks/thread.
    auto load_stage = [&](int it, int buf) {
        const uint32_t st = sbase + (uint32_t)buf * STAGE;
        const int k0 = it * 32;
        #pragma unroll
        for (int t = 0; t < 4; t++) {
            const int ch = tid + t * 256;
            const int r = ch >> 3, c = ch & 7;
            CP_ASYNC16(st +        (uint32_t)(r * ROWB + c * 16), A + (size_t)r * lda + k0 + c * 4);
            CP_ASYNC16(st + SM_B + (uint32_t)(r * ROWB + c * 16), B + (size_t)r * ldb + k0 + c * 4);
        }
    };

    // fragment byte offsets within a stage (conflict-free: 36-float row pad)
    uint32_t a_base[2], b_base[8];
    #pragma unroll
    for (int i = 0; i < 2; i++)
        a_base[i] = (uint32_t)(((wm * 32 + i * 16 + (lane >> 2)) * ROWF + (lane & 3)) * 4);
    #pragma unroll
    for (int j = 0; j < 8; j++)
        b_base[j] = (uint32_t)(SM_B + ((wn * 64 + j * 8 + (lane >> 2)) * ROWF + (lane & 3)) * 4);

    load_stage(0, 0); CP_COMMIT();
    load_stage(1, 1); CP_COMMIT();

    int buf = 0;                 // buffer holding stage `it`
    int nbuf = 2;                // buffer to fill with stage `it+2`
    for (int it = 0; it < niter; ++it) {
        CP_WAIT1();              // stage `it` resident (<=1 group pending)
        __syncthreads();         // all reads of stage it-1 retired -> nbuf reusable

        if (it + 2 < niter) load_stage(it + 2, nbuf);
        CP_COMMIT();             // commit (possibly empty) to keep group counts uniform

        const char* st = smem + buf * STAGE;
        #pragma unroll
        for (int ks = 0; ks < 4; ++ks) {
            const uint32_t ko = ks * 32;   // 8 floats per k8 step
            uint32_t a[2][4], b[8][2];
            #pragma unroll
            for (int i = 0; i < 2; i++) {
                const char* p = st + a_base[i] + ko;
                a[i][0] = *(const uint32_t*)(p);
                a[i][1] = *(const uint32_t*)(p + 8 * ROWB);
                a[i][2] = *(const uint32_t*)(p + 16);
                a[i][3] = *(const uint32_t*)(p + 8 * ROWB + 16);
            }
            #pragma unroll
            for (int j = 0; j < 8; j++) {
                const char* p = st + b_base[j] + ko;
                b[j][0] = *(const uint32_t*)(p);
                b[j][1] = *(const uint32_t*)(p + 16);
            }
            #pragma unroll
            for (int i = 0; i < 2; i++)
                #pragma unroll
                for (int j = 0; j < 8; j++)
                    mma_tf32(acc[i][j], a[i], b[j]);
        }

        buf  = (buf  == NSTG - 1) ? 0 : buf + 1;
        nbuf = (nbuf == NSTG - 1) ? 0 : nbuf + 1;
    }
}

// epilogue mapping: warp 4x2, warp tile 32x64
// m = wm*32 + i*16 + (lane>>2) (+8 for c2/c3); n = wn*64 + j*8 + (lane&3)*2 (+1)

// ---------------- kernel 1: QKV projection ----------------
__global__ __launch_bounds__(256, 2)
void qkv_gemm(const float* __restrict__ bq, const float* __restrict__ bk,
              const float* __restrict__ bv)
{
    extern __shared__ char smem[];
    const int z = blockIdx.z;
    const size_t rowb = (size_t)blockIdx.y * 128;
    const size_t colb = (size_t)blockIdx.x * 128;
    float acc[2][8][4];
    run_mainloop(acc, g_X + rowb * kH,
                      g_W + ((size_t)z * kH + colb) * kH,
                 kH, kH, kH / 32, smem);

    const float* bias = (z == 0) ? bq : (z == 1) ? bk : bv;
    const int tid = threadIdx.x, lane = tid & 31, wid = tid >> 5;
    const int wm = wid >> 1, wn = wid & 1;
    const int mloc0 = (int)rowb + wm * 32 + (lane >> 2);
    const int nloc0 = (int)colb + wn * 64 + (lane & 3) * 2;

    #pragma unroll
    for (int i = 0; i < 2; i++)
        #pragma unroll
        for (int j = 0; j < 8; j++) {
            const int n = nloc0 + j * 8;
            const float2 bb = *(const float2*)&bias[n];
            #pragma unroll
            for (int half = 0; half < 2; half++) {
                const int m = mloc0 + i * 16 + half * 8;
                const float v0 = rna_tf32(acc[i][j][half * 2 + 0] + bb.x);
                const float v1 = rna_tf32(acc[i][j][half * 2 + 1] + bb.y);
                if (z == 0) {
                    *(float2*)&g_Q[(size_t)m * kH + n] = make_float2(v0, v1);
                } else if (z == 1) {
                    *(float2*)&g_K[(size_t)m * kH + n] = make_float2(v0, v1);
                } else {
                    const int b = m >> 11, s = m & (kS - 1);
                    const size_t base = ((size_t)b * kH + n) * kS + s;
                    g_Vt[base]      = v0;
                    g_Vt[base + kS] = v1;
                }
            }
        }
}

// ---------------- kernel 2: scores = QK^T / 32 ----------------
__global__ __launch_bounds__(256, 2)
void scores_gemm()
{
    extern __shared__ char smem[];
    const int b = blockIdx.z;
    const size_t rowb = (size_t)b * kS + blockIdx.y * 128;
    const size_t colb = (size_t)b * kS + blockIdx.x * 128;
    float acc[2][8][4];
    run_mainloop(acc, g_Q + rowb * kH, g_K + colb * kH, kH, kH, kH / 32, smem);

    const int tid = threadIdx.x, lane = tid & 31, wid = tid >> 5;
    const int wm = wid >> 1, wn = wid & 1;
    const int mloc0 = blockIdx.y * 128 + wm * 32 + (lane >> 2);
    const int nloc0 = blockIdx.x * 128 + wn * 64 + (lane & 3) * 2;

    #pragma unroll
    for (int i = 0; i < 2; i++)
        #pragma unroll
        for (int j = 0; j < 8; j++) {
            const int n = nloc0 + j * 8;
            #pragma unroll
            for (int half = 0; half < 2; half++) {
                const int m = mloc0 + i * 16 + half * 8;
                float2 v = { acc[i][j][half * 2 + 0] * 0.03125f,
                             acc[i][j][half * 2 + 1] * 0.03125f };
                *(float2*)&g_Sc[((size_t)b * kS + m) * kS + n] = v;
            }
        }
}

// ---------------- kernel 3: softmax in place + tf32 rounding ----------------
__global__ __launch_bounds__(256)
void softmax_kernel()
{
    float* row = g_Sc + (size_t)blockIdx.x * kS;
    const int tid = threadIdx.x;

    float v[8];
    float mx = -3.0e38f;
    #pragma unroll
    for (int r = 0; r < 8; r++) { v[r] = row[tid + r * 256]; mx = fmaxf(mx, v[r]); }

    __shared__ float red[256];
    red[tid] = mx; __syncthreads();
    #pragma unroll
    for (int s2 = 128; s2 > 0; s2 >>= 1) {
        if (tid < s2) red[tid] = fmaxf(red[tid], red[tid + s2]);
        __syncthreads();
    }
    mx = red[0]; __syncthreads();

    float sum = 0.0f;
    #pragma unroll
    for (int r = 0; r < 8; r++) { v[r] = __expf(v[r] - mx); sum += v[r]; }
    red[tid] = sum; __syncthreads();
    #pragma unroll
    for (int s2 = 128; s2 > 0; s2 >>= 1) {
        if (tid < s2) red[tid] += red[tid + s2];
        __syncthreads();
    }
    const float inv = 1.0f / red[0];

    #pragma unroll
    for (int r = 0; r < 8; r++)
        row[tid + r * 256] = rna_tf32(v[r] * inv);
}

// ---------------- kernel 4: out = attn @ V ----------------
__global__ __launch_bounds__(256, 2)
void out_gemm(float* __restrict__ out)
{
    extern __shared__ char smem[];
    const int b = blockIdx.z;
    const size_t rowb = (size_t)b * kS + blockIdx.y * 128;
    const size_t colb = (size_t)b * kH + blockIdx.x * 128;
    float acc[2][8][4];
    run_mainloop(acc, g_Sc + rowb * kS, g_Vt + colb * kS, kS, kS, kS / 32, smem);

    const int tid = threadIdx.x, lane = tid & 31, wid = tid >> 5;
    const int wm = wid >> 1, wn = wid & 1;
    const int mloc0 = blockIdx.y * 128 + wm * 32 + (lane >> 2);
    const int nloc0 = blockIdx.x * 128 + wn * 64 + (lane & 3) * 2;

    #pragma unroll
    for (int i = 0; i < 2; i++)
        #pragma unroll
        for (int j = 0; j < 8; j++) {
            const int n = nloc0 + j * 8;
            #pragma unroll
            for (int half = 0; half < 2; half++) {
                const int m = mloc0 + i * 16 + half * 8;
                float2 v = { acc[i][j][half * 2 + 0], acc[i][j][half * 2 + 1] };
                *(float2*)&out[((size_t)b * kS + m) * kH + n] = v;
            }
        }
}

// ---------------- conversion prepass: fp32 -> tf32-rounded fp32 ----------------
__global__ __launch_bounds__(256)
void convX_kernel(const float* __restrict__ X)
{
    const size_t i = ((size_t)blockIdx.x * 256 + threadIdx.x) * 4;
    float4 x = *(const float4*)&X[i];
    x.x = rna_tf32(x.x); x.y = rna_tf32(x.y);
    x.z = rna_tf32(x.z); x.w = rna_tf32(x.w);
    *(float4*)&g_X[i] = x;
}

__global__ __launch_bounds__(256)
void convW_kernel(const float* __restrict__ Wq, const float* __restrict__ Wk,
                  const float* __restrict__ Wv)
{
    const size_t i = ((size_t)blockIdx.x * 256 + threadIdx.x) * 4;
    const int z = (int)(i >> 20);
    const size_t r = i & ((size_t)kH * kH - 1);
    const float* W = (z == 0) ? Wq : (z == 1) ? Wk : Wv;
    float4 x = *(const float4*)&W[r];
    x.x = rna_tf32(x.x); x.y = rna_tf32(x.y);
    x.z = rna_tf32(x.z); x.w = rna_tf32(x.w);
    *(float4*)&g_W[i] = x;
}

// ---------------- entry point ----------------
extern "C" void kernel_launch(void* const* d_in, const int* in_sizes, int n_in,
                              void* d_out, int out_size)
{
    const float* X  = (const float*)d_in[0];
    const float* Wq = (const float*)d_in[1];
    const float* bq = (const float*)d_in[2];
    const float* Wk = (const float*)d_in[3];
    const float* bk = (const float*)d_in[4];
    const float* Wv = (const float*)d_in[5];
    const float* bv = (const float*)d_in[6];
    float* out = (float*)d_out;

    static bool attr_done = false;
    if (!attr_done) {
        cudaFuncSetAttribute(qkv_gemm,    cudaFuncAttributeMaxDynamicSharedMemorySize, SMEM_BYTES);
        cudaFuncSetAttribute(scores_gemm, cudaFuncAttributeMaxDynamicSharedMemorySize, SMEM_BYTES);
        cudaFuncSetAttribute(out_gemm,    cudaFuncAttributeMaxDynamicSharedMemorySize, SMEM_BYTES);
        attr_done = true;
    }

    convX_kernel<<<(int)((size_t)kM * kH / 4 / 256), 256>>>(X);
    convW_kernel<<<(int)((size_t)3 * kH * kH / 4 / 256), 256>>>(Wq, Wk, Wv);
    qkv_gemm   <<<dim3(kH / 128, kM / 128, 3), 256, SMEM_BYTES>>>(bq, bk, bv);
    scores_gemm<<<dim3(kS / 128, kS / 128, kB), 256, SMEM_BYTES>>>();
    softmax_kernel<<<kM, 256>>>();
    out_gemm   <<<dim3(kH / 128, kS / 128, kB), 256, SMEM_BYTES>>>(out);
}